// round 9
// baseline (speedup 1.0000x reference)
#include <cuda_runtime.h>

#define NB 8
#define NS 2048
#define ND 768
#define NH 64
#define NQT 32            // q-tiles of 64
#define SKA 68            // attn smem stride (floats), 68 % 32 == 4 -> conflict-free LDSM
#define PXS 36            // proj X smem stride   (36 % 32 == 4)
#define PWS 36            // proj Wt smem stride  (36 % 32 == 4)

__device__ float g_Q[NB * NS * NH];
__device__ float g_K[NB * NS * NH];
__device__ float g_V[NB * NS * NH];
__device__ float g_Wt[3 * NH * ND];     // [n=z*64+h][k], tf32-rounded bits

// split-K partials: [half][b][qt] -> 64x64 unnormalized O, plus per-row m,l
__device__ float g_Op[2 * NB * NQT * 64 * 64];
__device__ float g_M[2 * NB * NQT * 64];
__device__ float g_L[2 * NB * NQT * 64];

// ---------------------------------------------------------------------------
// helpers
// ---------------------------------------------------------------------------
__device__ __forceinline__ unsigned f2tf(float f) {
    unsigned u;
    asm("cvt.rna.tf32.f32 %0, %1;" : "=r"(u) : "f"(f));
    return u;
}
__device__ __forceinline__ uint4 f4tf(float4 v) {
    uint4 r;
    r.x = f2tf(v.x); r.y = f2tf(v.y); r.z = f2tf(v.z); r.w = f2tf(v.w);
    return r;
}
__device__ __forceinline__ void mma8(float c[4],
                                     unsigned a0, unsigned a1, unsigned a2, unsigned a3,
                                     unsigned b0, unsigned b1) {
    asm("mma.sync.aligned.m16n8k8.row.col.f32.tf32.tf32.f32 "
        "{%0,%1,%2,%3}, {%4,%5,%6,%7}, {%8,%9}, {%0,%1,%2,%3};"
        : "+f"(c[0]), "+f"(c[1]), "+f"(c[2]), "+f"(c[3])
        : "r"(a0), "r"(a1), "r"(a2), "r"(a3), "r"(b0), "r"(b1));
}
__device__ __forceinline__ void ldsm4(unsigned &r0, unsigned &r1,
                                      unsigned &r2, unsigned &r3, unsigned addr) {
    asm volatile("ldmatrix.sync.aligned.m8n8.x4.shared.b16 {%0,%1,%2,%3}, [%4];"
                 : "=r"(r0), "=r"(r1), "=r"(r2), "=r"(r3) : "r"(addr));
}

// ---------------------------------------------------------------------------
// Kernel 0: transpose + tf32-round the three weight matrices into g_Wt[n][k].
// grid (ND/32, 64/32, 3), block (32, 8). Coalesced read and write.
// ---------------------------------------------------------------------------
__global__ void wt_kernel(const float* __restrict__ Wq,
                          const float* __restrict__ Wk,
                          const float* __restrict__ Wv)
{
    __shared__ float tb[32][33];
    const int z = blockIdx.z;
    const float* __restrict__ W = (z == 0) ? Wq : (z == 1) ? Wk : Wv;
    const int k0 = blockIdx.x * 32, n0 = blockIdx.y * 32;
    const int tx = threadIdx.x, ty = threadIdx.y;
#pragma unroll
    for (int i = 0; i < 4; ++i)
        tb[ty + i * 8][tx] = W[(size_t)(k0 + ty + i * 8) * NH + n0 + tx];
    __syncthreads();
#pragma unroll
    for (int i = 0; i < 4; ++i)
        g_Wt[(size_t)(z * NH + n0 + ty + i * 8) * ND + k0 + tx] =
            __uint_as_float(f2tf(tb[tx][ty + i * 8]));
}

// ---------------------------------------------------------------------------
// Kernel 1: fused QKV projection. Out[m, 0:192] = X[m, :] x Wt^T, m-tile 64.
// 128 threads / 4 warps, warp w owns m rows [w*16, w*16+16); 24 n-tiles of 8
// (Q: 0-7, K: 8-15, V: 16-23). All fragments via ldmatrix from smem.
// X converted to tf32 on smem store (once); Wt already tf32 in global.
// ---------------------------------------------------------------------------
__global__ __launch_bounds__(128, 2) void proj_kernel(const float* __restrict__ X)
{
    __shared__ float Xs[64 * PXS];        // [m][k]  9.2 KB
    __shared__ float Ws[192 * PWS];       // [n][k] 27.6 KB

    const int row0 = blockIdx.x * 64;
    const int tid  = threadIdx.x;
    const int wrp  = tid >> 5;
    const int lane = tid & 31;
    const int g    = lane >> 2;
    const int t    = lane & 3;
    const int w16  = wrp * 16;

    float acc[24][4];
#pragma unroll
    for (int nt = 0; nt < 24; ++nt)
#pragma unroll
        for (int r = 0; r < 4; ++r) acc[nt][r] = 0.0f;

    // ldmatrix lane addresses
    const unsigned smbX = (unsigned)__cvta_generic_to_shared(Xs);
    const unsigned smbW = (unsigned)__cvta_generic_to_shared(Ws);
    const int rowA = w16 + (lane & 15);
    const int colA = (lane >> 4) * 4;
    const unsigned aX = smbX + (unsigned)((rowA * PXS + colA) * 4);
    const int rowB = (lane & 7) | ((lane >> 1) & 8);
    const int colB = ((lane >> 3) & 1) * 4;
    const unsigned bW = smbW + (unsigned)((rowB * PWS + colB) * 4);

    const int xr = tid >> 1;              // 0..63
    const int xc = (tid & 1) * 16;        // 0 or 16

    for (int kk = 0; kk < ND; kk += 32) {
        // X tile 64x32, tf32-rounded
#pragma unroll
        for (int u = 0; u < 4; ++u) {
            float4 v = *reinterpret_cast<const float4*>(
                X + (size_t)(row0 + xr) * ND + kk + xc + u * 4);
            *reinterpret_cast<uint4*>(&Xs[xr * PXS + xc + u * 4]) = f4tf(v);
        }
        // Wt tile 192x32 (already tf32 bits)
#pragma unroll
        for (int it = 0; it < 12; ++it) {
            const int fi = it * 128 + tid;        // 0..1535 float4s
            const int n  = fi >> 3;
            const int c4 = (fi & 7) * 4;
            *reinterpret_cast<float4*>(&Ws[n * PWS + c4]) =
                *reinterpret_cast<const float4*>(&g_Wt[(size_t)n * ND + kk + c4]);
        }
        __syncthreads();

#pragma unroll
        for (int dc = 0; dc < 4; ++dc) {
            unsigned a0, a1, a2, a3;
            ldsm4(a0, a1, a2, a3, aX + dc * 32);
#pragma unroll
            for (int p = 0; p < 12; ++p) {
                unsigned b0, b1, b2, b3;
                ldsm4(b0, b1, b2, b3, bW + p * (16 * PWS * 4) + dc * 32);
                mma8(acc[2 * p],     a0, a1, a2, a3, b0, b1);
                mma8(acc[2 * p + 1], a0, a1, a2, a3, b2, b3);
            }
        }
        __syncthreads();
    }

    // epilogue: nt 0-7 -> Q, 8-15 -> K, 16-23 -> V
#pragma unroll
    for (int nt = 0; nt < 24; ++nt) {
        float* __restrict__ Out = (nt < 8) ? g_Q : (nt < 16) ? g_K : g_V;
        const int col = (nt & 7) * 8 + 2 * t;
        const int rA  = row0 + w16 + g;
        *reinterpret_cast<float2*>(Out + (size_t)rA * NH + col) =
            make_float2(acc[nt][0], acc[nt][1]);
        *reinterpret_cast<float2*>(Out + (size_t)(rA + 8) * NH + col) =
            make_float2(acc[nt][2], acc[nt][3]);
    }
}

// ---------------------------------------------------------------------------
// Kernel 2: causal flash attention, tf32 mma + ldmatrix + split-K x2.
// (unchanged from R8 — proven at 148 us total)
// ---------------------------------------------------------------------------
__global__ __launch_bounds__(128, 3) void attn_kernel()
{
    extern __shared__ float sm[];
    float* __restrict__ Qs = sm;                 // [64][68]
    float* __restrict__ Ks = sm + 64 * SKA;      // [64][68]
    float* __restrict__ Ps = sm + 2 * 64 * SKA;  // [64][68]
    float* __restrict__ Vt = sm + 3 * 64 * SKA;  // [64][68] V transposed [h][k]

    const int b    = blockIdx.y;
    const int qt   = (NQT - 1) - blockIdx.x;
    const int half = blockIdx.z;
    const int q0   = qt * 64;
    const int tid  = threadIdx.x;
    const int wrp  = tid >> 5;
    const int lane = tid & 31;
    const int g    = lane >> 2;
    const int t    = lane & 3;
    const int w16  = wrp * 16;

    const int T  = qt + 1;
    const int h0 = (T + 1) >> 1;
    const int tb = half ? h0 : 0;
    const int te = half ? T  : h0;

    const float* __restrict__ Qb = g_Q + (size_t)b * NS * NH;
    const float* __restrict__ Kb = g_K + (size_t)b * NS * NH;
    const float* __restrict__ Vb = g_V + (size_t)b * NS * NH;

    const unsigned smb = (unsigned)__cvta_generic_to_shared(sm);
    const int rowA = w16 + (lane & 15);
    const int colA = (lane >> 4) * 4;
    const unsigned aQ = smb + (unsigned)((rowA * SKA + colA) * 4);
    const unsigned aP = aQ + 2u * 64 * SKA * 4;
    const int rowB = (lane & 7) | ((lane >> 1) & 8);
    const int colB = ((lane >> 3) & 1) * 4;
    const unsigned bK = smb + 1u * 64 * SKA * 4 + (unsigned)((rowB * SKA + colB) * 4);
    const unsigned bV = smb + 3u * 64 * SKA * 4 + (unsigned)((rowB * SKA + colB) * 4);

    {
        const int r = tid >> 1;
        const int c = (tid & 1) * 32;
        const float4* qp = reinterpret_cast<const float4*>(
            Qb + (size_t)(q0 + r) * NH + c);
#pragma unroll
        for (int u = 0; u < 8; ++u)
            *reinterpret_cast<uint4*>(&Qs[r * SKA + c + u * 4]) = f4tf(qp[u]);
    }

    float o[8][4];
#pragma unroll
    for (int nt = 0; nt < 8; ++nt)
#pragma unroll
        for (int r = 0; r < 4; ++r) o[nt][r] = 0.0f;
    float mA = -1e30f, mB = -1e30f;
    float lA = 0.0f,   lB = 0.0f;

    for (int kt = tb; kt < te; ++kt) {
        const int k0 = kt * 64;

        __syncthreads();
        {
            const int r = tid >> 1;
            const int c = (tid & 1) * 32;
            const float4* kp = reinterpret_cast<const float4*>(
                Kb + (size_t)(k0 + r) * NH + c);
#pragma unroll
            for (int u = 0; u < 8; ++u)
                *reinterpret_cast<uint4*>(&Ks[r * SKA + c + u * 4]) = f4tf(kp[u]);
        }
        {
            const int rv = tid & 63;
            const int hb = (tid >> 6) * 32;
            const float4* vp = reinterpret_cast<const float4*>(
                Vb + (size_t)(k0 + rv) * NH + hb);
#pragma unroll
            for (int u = 0; u < 8; ++u) {
                float4 v = vp[u];
                const int h = hb + u * 4;
                Vt[(h + 0) * SKA + rv] = __uint_as_float(f2tf(v.x));
                Vt[(h + 1) * SKA + rv] = __uint_as_float(f2tf(v.y));
                Vt[(h + 2) * SKA + rv] = __uint_as_float(f2tf(v.z));
                Vt[(h + 3) * SKA + rv] = __uint_as_float(f2tf(v.w));
            }
        }
        __syncthreads();

        float s[8][4];
#pragma unroll
        for (int nt = 0; nt < 8; ++nt)
#pragma unroll
            for (int r = 0; r < 4; ++r) s[nt][r] = 0.0f;

#pragma unroll
        for (int dc = 0; dc < 8; ++dc) {
            unsigned a0, a1, a2, a3;
            ldsm4(a0, a1, a2, a3, aQ + dc * 32);
#pragma unroll
            for (int p = 0; p < 4; ++p) {
                unsigned b0, b1, b2, b3;
                ldsm4(b0, b1, b2, b3, bK + p * (16 * SKA * 4) + dc * 32);
                mma8(s[2 * p],     a0, a1, a2, a3, b0, b1);
                mma8(s[2 * p + 1], a0, a1, a2, a3, b2, b3);
            }
        }

        if (kt == qt) {
            const int rA = w16 + g, rB = w16 + g + 8;
#pragma unroll
            for (int nt = 0; nt < 8; ++nt) {
                const int c0 = nt * 8 + 2 * t, c1 = c0 + 1;
                s[nt][0] = (c0 <= rA) ? s[nt][0] * 0.125f : -1e30f;
                s[nt][1] = (c1 <= rA) ? s[nt][1] * 0.125f : -1e30f;
                s[nt][2] = (c0 <= rB) ? s[nt][2] * 0.125f : -1e30f;
                s[nt][3] = (c1 <= rB) ? s[nt][3] * 0.125f : -1e30f;
            }
        } else {
#pragma unroll
            for (int nt = 0; nt < 8; ++nt)
#pragma unroll
                for (int r = 0; r < 4; ++r) s[nt][r] *= 0.125f;
        }

        float cmA = -1e30f, cmB = -1e30f;
#pragma unroll
        for (int nt = 0; nt < 8; ++nt) {
            cmA = fmaxf(cmA, fmaxf(s[nt][0], s[nt][1]));
            cmB = fmaxf(cmB, fmaxf(s[nt][2], s[nt][3]));
        }
        cmA = fmaxf(cmA, __shfl_xor_sync(0xffffffffu, cmA, 1));
        cmA = fmaxf(cmA, __shfl_xor_sync(0xffffffffu, cmA, 2));
        cmB = fmaxf(cmB, __shfl_xor_sync(0xffffffffu, cmB, 1));
        cmB = fmaxf(cmB, __shfl_xor_sync(0xffffffffu, cmB, 2));

        const float mnA = fmaxf(mA, cmA);
        const float mnB = fmaxf(mB, cmB);
        const float cA  = __expf(mA - mnA);
        const float cB  = __expf(mB - mnB);
        mA = mnA; mB = mnB;
        lA *= cA; lB *= cB;
#pragma unroll
        for (int nt = 0; nt < 8; ++nt) {
            o[nt][0] *= cA; o[nt][1] *= cA;
            o[nt][2] *= cB; o[nt][3] *= cB;
        }
#pragma unroll
        for (int nt = 0; nt < 8; ++nt) {
            s[nt][0] = __expf(s[nt][0] - mnA);
            s[nt][1] = __expf(s[nt][1] - mnA);
            s[nt][2] = __expf(s[nt][2] - mnB);
            s[nt][3] = __expf(s[nt][3] - mnB);
            lA += s[nt][0] + s[nt][1];
            lB += s[nt][2] + s[nt][3];
        }

#pragma unroll
        for (int nt = 0; nt < 8; ++nt) {
            *reinterpret_cast<uint2*>(&Ps[(w16 + g) * SKA + nt * 8 + 2 * t]) =
                make_uint2(f2tf(s[nt][0]), f2tf(s[nt][1]));
            *reinterpret_cast<uint2*>(&Ps[(w16 + g + 8) * SKA + nt * 8 + 2 * t]) =
                make_uint2(f2tf(s[nt][2]), f2tf(s[nt][3]));
        }
        __syncwarp();

#pragma unroll
        for (int kc = 0; kc < 8; ++kc) {
            unsigned a0, a1, a2, a3;
            ldsm4(a0, a1, a2, a3, aP + kc * 32);
#pragma unroll
            for (int p = 0; p < 4; ++p) {
                unsigned b0, b1, b2, b3;
                ldsm4(b0, b1, b2, b3, bV + p * (16 * SKA * 4) + kc * 32);
                mma8(o[2 * p],     a0, a1, a2, a3, b0, b1);
                mma8(o[2 * p + 1], a0, a1, a2, a3, b2, b3);
            }
        }
        __syncwarp();
    }

    lA += __shfl_xor_sync(0xffffffffu, lA, 1);
    lA += __shfl_xor_sync(0xffffffffu, lA, 2);
    lB += __shfl_xor_sync(0xffffffffu, lB, 1);
    lB += __shfl_xor_sync(0xffffffffu, lB, 2);

    const size_t slot = ((size_t)half * NB + b) * NQT + qt;
    float* op = g_Op + slot * 64 * 64;
#pragma unroll
    for (int nt = 0; nt < 8; ++nt) {
        *reinterpret_cast<float2*>(op + (w16 + g) * 64 + nt * 8 + 2 * t) =
            make_float2(o[nt][0], o[nt][1]);
        *reinterpret_cast<float2*>(op + (w16 + g + 8) * 64 + nt * 8 + 2 * t) =
            make_float2(o[nt][2], o[nt][3]);
    }
    if (t == 0) {
        g_M[slot * 64 + w16 + g]     = mA;
        g_M[slot * 64 + w16 + g + 8] = mB;
        g_L[slot * 64 + w16 + g]     = lA;
        g_L[slot * 64 + w16 + g + 8] = lB;
    }
}

// ---------------------------------------------------------------------------
// Kernel 3: merge split-K partials. grid (32, NB), 256 threads.
// ---------------------------------------------------------------------------
__global__ __launch_bounds__(256) void merge_kernel(float* __restrict__ out)
{
    const int qt  = blockIdx.x;
    const int b   = blockIdx.y;
    const int tid = threadIdx.x;
    const int r   = tid >> 2;
    const int cs  = (tid & 3) * 16;

    const size_t s0 = ((size_t)0 * NB + b) * NQT + qt;
    const size_t s1 = ((size_t)1 * NB + b) * NQT + qt;

    const float m0 = g_M[s0 * 64 + r];
    const float m1 = g_M[s1 * 64 + r];
    const float l0 = g_L[s0 * 64 + r];
    const float l1 = g_L[s1 * 64 + r];

    const float M  = fmaxf(m0, m1);
    float f0 = __expf(m0 - M);
    float f1 = __expf(m1 - M);
    const float inv = 1.0f / (l0 * f0 + l1 * f1);
    f0 *= inv; f1 *= inv;

    const float4* p0 = reinterpret_cast<const float4*>(g_Op + s0 * 4096 + r * 64 + cs);
    const float4* p1 = reinterpret_cast<const float4*>(g_Op + s1 * 4096 + r * 64 + cs);
    float4* po = reinterpret_cast<float4*>(
        out + ((size_t)b * NS + qt * 64 + r) * NH + cs);

#pragma unroll
    for (int u = 0; u < 4; ++u) {
        float4 a = p0[u], c = p1[u];
        po[u] = make_float4(a.x * f0 + c.x * f1, a.y * f0 + c.y * f1,
                            a.z * f0 + c.z * f1, a.w * f0 + c.w * f1);
    }
}

// ---------------------------------------------------------------------------
extern "C" void kernel_launch(void* const* d_in, const int* in_sizes, int n_in,
                              void* d_out, int out_size)
{
    const float* X  = (const float*)d_in[0];
    const float* Wq = (const float*)d_in[1];
    const float* Wk = (const float*)d_in[2];
    const float* Wv = (const float*)d_in[3];
    float* out = (float*)d_out;

    const int attn_smem = 4 * 64 * SKA * (int)sizeof(float);   // 69632 B
    cudaFuncSetAttribute(attn_kernel,
                         cudaFuncAttributeMaxDynamicSharedMemorySize, attn_smem);

    wt_kernel<<<dim3(ND / 32, NH / 32, 3), dim3(32, 8)>>>(Wq, Wk, Wv);
    proj_kernel<<<(NB * NS) / 64, 128>>>(X);
    attn_kernel<<<dim3(NQT, NB, 2), 128, attn_smem>>>();
    merge_kernel<<<dim3(NQT, NB), 256>>>(out);
}